// round 4
// baseline (speedup 1.0000x reference)
#include <cuda_runtime.h>

#define BB 8
#define TT 2048
#define DD 256
#define BT (BB*TT)           // 16384
#define EPS_SUM 1e-8f
#define EPS_LN  1e-6f

// ---------------- scratch (device globals; no allocations allowed) ----------
__device__ float g_vb1[BT*DD];
__device__ float g_vb2[BT*DD];
__device__ float g_ab1[BT*DD];
__device__ float g_ab2[BT*DD];
__device__ float g_S[(size_t)BB*TT*TT];   // 134 MB scores
__device__ float g_vout[BT*DD];
__device__ float g_aout[BT*DD];
__device__ float g_tmpv[BT*DD];
__device__ float g_tmpa[BT*DD];
__device__ float g_srow[BT];
__device__ float g_scol[BT];
__device__ float g_mrow[BT];
__device__ float g_mcol[BT];

// ---------------- shared 128x128x16 tile compute ----------------------------
__device__ __forceinline__ void tile_compute(const float (*As)[132], const float (*Bs)[132],
                                             float (&acc)[8][8], int ty, int tx) {
#pragma unroll
    for (int k = 0; k < 16; k++) {
        float ra[8], rb[8];
#pragma unroll
        for (int i = 0; i < 8; i++) ra[i] = As[k][ty*8 + i];
#pragma unroll
        for (int j = 0; j < 8; j++) rb[j] = Bs[k][tx*8 + j];
#pragma unroll
        for (int i = 0; i < 8; i++)
#pragma unroll
            for (int j = 0; j < 8; j++)
                acc[i][j] = fmaf(ra[i], rb[j], acc[i][j]);
    }
}

// ---------------- K1: four input GEMMs X @ W^T, relu ------------------------
__global__ __launch_bounds__(256) void k_in_gemm(const float* __restrict__ v_f,
                                                 const float* __restrict__ a_f,
                                                 const float* __restrict__ Wv1,
                                                 const float* __restrict__ Wv2,
                                                 const float* __restrict__ Wa1,
                                                 const float* __restrict__ Wa2) {
    __shared__ float As[16][132];
    __shared__ float Bs[16][132];
    int z = blockIdx.z;
    const float* X = (z < 2) ? v_f : a_f;
    const float* W = (z == 0) ? Wv1 : (z == 1) ? Wv2 : (z == 2) ? Wa1 : Wa2;
    float* C = (z == 0) ? g_vb1 : (z == 1) ? g_vb2 : (z == 2) ? g_ab1 : g_ab2;
    int m0 = blockIdx.y * 128, n0 = blockIdx.x * 128;
    int t = threadIdx.x, tx = t & 15, ty = t >> 4;
    float acc[8][8];
#pragma unroll
    for (int i = 0; i < 8; i++)
#pragma unroll
        for (int j = 0; j < 8; j++) acc[i][j] = 0.f;

    for (int k0 = 0; k0 < DD; k0 += 16) {
#pragma unroll
        for (int i = 0; i < 8; i++) {
            int lin = t + i*256;
            int m = lin >> 4, k = lin & 15;
            As[k][m] = X[(m0+m)*DD + k0 + k];
            Bs[k][m] = W[(n0+m)*DD + k0 + k];
        }
        __syncthreads();
        tile_compute(As, Bs, acc, ty, tx);
        __syncthreads();
    }
#pragma unroll
    for (int i = 0; i < 8; i++) {
        int m = m0 + ty*8 + i;
#pragma unroll
        for (int j = 0; j < 8; j++) {
            int n = n0 + tx*8 + j;
            C[m*DD + n] = fmaxf(acc[i][j], 0.f);
        }
    }
}

// ---------------- K2: scores S = relu(Vb2 @ Ab1^T / 16) ---------------------
__global__ __launch_bounds__(256) void k_scores() {
    __shared__ float As[16][132];
    __shared__ float Bs[16][132];
    int b = blockIdx.z;
    const float* A = g_vb2 + b*TT*DD;
    const float* Bm = g_ab1 + b*TT*DD;
    float* C = g_S + (size_t)b*TT*TT;
    int m0 = blockIdx.y * 128, n0 = blockIdx.x * 128;
    int t = threadIdx.x, tx = t & 15, ty = t >> 4;
    float acc[8][8];
#pragma unroll
    for (int i = 0; i < 8; i++)
#pragma unroll
        for (int j = 0; j < 8; j++) acc[i][j] = 0.f;

    for (int k0 = 0; k0 < DD; k0 += 16) {
#pragma unroll
        for (int i = 0; i < 8; i++) {
            int lin = t + i*256;
            int m = lin >> 4, k = lin & 15;
            As[k][m] = A[(m0+m)*DD + k0 + k];
            Bs[k][m] = Bm[(n0+m)*DD + k0 + k];
        }
        __syncthreads();
        tile_compute(As, Bs, acc, ty, tx);
        __syncthreads();
    }
#pragma unroll
    for (int i = 0; i < 8; i++) {
        int m = m0 + ty*8 + i;
#pragma unroll
        for (int j = 0; j < 8; j++) {
            int n = n0 + tx*8 + j;
            C[m*TT + n] = fmaxf(acc[i][j] * 0.0625f, 0.f);
        }
    }
}

// ---------------- row sums (plain and masked) --------------------------------
__global__ void k_rowsum(const float* __restrict__ thr_p, int masked) {
    int row = blockIdx.x;                           // b*2048 + v
    const float* p = g_S + (size_t)row * TT;
    float tr = -1.f;
    if (masked) tr = thr_p[0] * (g_srow[row] + EPS_SUM);
    float s = 0.f;
    for (int i = threadIdx.x; i < TT; i += 256) {
        float x = p[i];
        if (x > tr) s += x;
    }
    __shared__ float red[256];
    red[threadIdx.x] = s;
    __syncthreads();
    for (int st = 128; st > 0; st >>= 1) {
        if (threadIdx.x < st) red[threadIdx.x] += red[threadIdx.x + st];
        __syncthreads();
    }
    if (threadIdx.x == 0) {
        if (masked) g_mrow[row] = red[0]; else g_srow[row] = red[0];
    }
}

// ---------------- column sums (plain and masked) -----------------------------
__global__ void k_colsum(const float* __restrict__ thr_p, int masked) {
    int b = blockIdx.y;
    int a = blockIdx.x * 256 + threadIdx.x;
    const float* base = g_S + (size_t)b*TT*TT + a;
    float tr = -1.f;
    if (masked) tr = thr_p[0] * (g_scol[b*TT + a] + EPS_SUM);
    float s = 0.f;
#pragma unroll 16
    for (int v = 0; v < TT; v++) {
        float x = base[(size_t)v * TT];
        if (x > tr) s += x;
    }
    if (masked) g_mcol[b*TT + a] = s; else g_scol[b*TT + a] = s;
}

// ---------------- K4: v_out = v_f + (masked S) @ Ab2 * rcp_row ---------------
__global__ __launch_bounds__(256) void k_agg_v(const float* __restrict__ v_f,
                                               const float* __restrict__ thr_p) {
    __shared__ float As[16][132];
    __shared__ float Bs[16][132];
    __shared__ float trs[128];
    int b = blockIdx.z;
    int m0 = blockIdx.y * 128;   // v
    int n0 = blockIdx.x * 128;   // h
    int t = threadIdx.x, tx = t & 15, ty = t >> 4;
    float thr = thr_p[0];
    if (t < 128) trs[t] = thr * (g_srow[b*TT + m0 + t] + EPS_SUM);
    __syncthreads();
    const float* Sb = g_S + (size_t)b*TT*TT;
    const float* Bm = g_ab2 + b*TT*DD;
    float acc[8][8];
#pragma unroll
    for (int i = 0; i < 8; i++)
#pragma unroll
        for (int j = 0; j < 8; j++) acc[i][j] = 0.f;

    for (int k0 = 0; k0 < TT; k0 += 16) {
#pragma unroll
        for (int i = 0; i < 8; i++) {
            int lin = t + i*256;
            int m = lin >> 4, k = lin & 15;
            float x = Sb[(m0+m)*TT + k0 + k];
            As[k][m] = (x > trs[m]) ? x : 0.f;
        }
#pragma unroll
        for (int i = 0; i < 8; i++) {
            int lin = t + i*256;
            int k = lin >> 7, n = lin & 127;
            Bs[k][n] = Bm[(k0+k)*DD + n0 + n];
        }
        __syncthreads();
        tile_compute(As, Bs, acc, ty, tx);
        __syncthreads();
    }
#pragma unroll
    for (int i = 0; i < 8; i++) {
        int row = b*TT + m0 + ty*8 + i;
        float rcp = 1.f / (g_mrow[row] + EPS_SUM * (g_srow[row] + EPS_SUM));
#pragma unroll
        for (int j = 0; j < 8; j++) {
            int n = n0 + tx*8 + j;
            g_vout[row*DD + n] = v_f[row*DD + n] + acc[i][j] * rcp;
        }
    }
}

// ---------------- K5: a_out = a_f + (masked S)^T @ Vb1 * rcp_col -------------
__global__ __launch_bounds__(256) void k_agg_a(const float* __restrict__ a_f,
                                               const float* __restrict__ thr_p) {
    __shared__ float As[16][132];
    __shared__ float Bs[16][132];
    __shared__ float tcs[128];
    int b = blockIdx.z;
    int m0 = blockIdx.y * 128;   // a
    int n0 = blockIdx.x * 128;   // h
    int t = threadIdx.x, tx = t & 15, ty = t >> 4;
    float thr = thr_p[0];
    if (t < 128) tcs[t] = thr * (g_scol[b*TT + m0 + t] + EPS_SUM);
    __syncthreads();
    const float* Sb = g_S + (size_t)b*TT*TT;
    const float* Bm = g_vb1 + b*TT*DD;
    float acc[8][8];
#pragma unroll
    for (int i = 0; i < 8; i++)
#pragma unroll
        for (int j = 0; j < 8; j++) acc[i][j] = 0.f;

    for (int k0 = 0; k0 < TT; k0 += 16) {
#pragma unroll
        for (int i = 0; i < 8; i++) {
            int lin = t + i*256;
            int k = lin >> 7, m = lin & 127;     // read S[v=k0+k][a=m0+m], coalesced in a
            float x = Sb[(size_t)(k0+k)*TT + m0 + m];
            As[k][m] = (x > tcs[m]) ? x : 0.f;
        }
#pragma unroll
        for (int i = 0; i < 8; i++) {
            int lin = t + i*256;
            int k = lin >> 7, n = lin & 127;
            Bs[k][n] = Bm[(k0+k)*DD + n0 + n];
        }
        __syncthreads();
        tile_compute(As, Bs, acc, ty, tx);
        __syncthreads();
    }
#pragma unroll
    for (int i = 0; i < 8; i++) {
        int row = b*TT + m0 + ty*8 + i;
        float rcp = 1.f / (g_mcol[row] + EPS_SUM * (g_scol[row] + EPS_SUM));
#pragma unroll
        for (int j = 0; j < 8; j++) {
            int n = n0 + tx*8 + j;
            g_aout[row*DD + n] = a_f[row*DD + n] + acc[i][j] * rcp;
        }
    }
}

// ---------------- K6a: output GEMMs + relu -----------------------------------
__global__ __launch_bounds__(256) void k_out_gemm(const float* __restrict__ Wvfc,
                                                  const float* __restrict__ Wac) {
    __shared__ float As[16][132];
    __shared__ float Bs[16][132];
    int z = blockIdx.z;
    const float* X = z ? g_aout : g_vout;
    const float* W = z ? Wac : Wvfc;
    float* C = z ? g_tmpa : g_tmpv;
    int m0 = blockIdx.y * 128, n0 = blockIdx.x * 128;
    int t = threadIdx.x, tx = t & 15, ty = t >> 4;
    float acc[8][8];
#pragma unroll
    for (int i = 0; i < 8; i++)
#pragma unroll
        for (int j = 0; j < 8; j++) acc[i][j] = 0.f;

    for (int k0 = 0; k0 < DD; k0 += 16) {
#pragma unroll
        for (int i = 0; i < 8; i++) {
            int lin = t + i*256;
            int m = lin >> 4, k = lin & 15;
            As[k][m] = X[(m0+m)*DD + k0 + k];
            Bs[k][m] = W[(n0+m)*DD + k0 + k];
        }
        __syncthreads();
        tile_compute(As, Bs, acc, ty, tx);
        __syncthreads();
    }
#pragma unroll
    for (int i = 0; i < 8; i++) {
        int m = m0 + ty*8 + i;
#pragma unroll
        for (int j = 0; j < 8; j++) {
            int n = n0 + tx*8 + j;
            C[m*DD + n] = fmaxf(acc[i][j], 0.f);
        }
    }
}

// ---------------- K6b: layernorm + combine -----------------------------------
__global__ void k_ln(const float* __restrict__ ln_scale, const float* __restrict__ ln_bias,
                     float* __restrict__ out) {
    int row = blockIdx.x * 8 + (threadIdx.x >> 5);
    int lane = threadIdx.x & 31;
    const float* xv = g_tmpv + row*DD;
    const float* xa = g_tmpa + row*DD;
    float v[8], a[8];
#pragma unroll
    for (int i = 0; i < 8; i++) { v[i] = xv[lane + i*32]; a[i] = xa[lane + i*32]; }
    float sv = 0.f, sa = 0.f;
#pragma unroll
    for (int i = 0; i < 8; i++) { sv += v[i]; sa += a[i]; }
#pragma unroll
    for (int o = 16; o > 0; o >>= 1) {
        sv += __shfl_xor_sync(0xffffffffu, sv, o);
        sa += __shfl_xor_sync(0xffffffffu, sa, o);
    }
    float muv = sv * (1.f/256.f), mua = sa * (1.f/256.f);
    float qv = 0.f, qa = 0.f;
#pragma unroll
    for (int i = 0; i < 8; i++) {
        float dv = v[i] - muv; qv += dv*dv;
        float da = a[i] - mua; qa += da*da;
    }
#pragma unroll
    for (int o = 16; o > 0; o >>= 1) {
        qv += __shfl_xor_sync(0xffffffffu, qv, o);
        qa += __shfl_xor_sync(0xffffffffu, qa, o);
    }
    float rv = rsqrtf(qv * (1.f/256.f) + EPS_LN);
    float ra = rsqrtf(qa * (1.f/256.f) + EPS_LN);

    float* avp = out;
    float* vp  = out + (size_t)BT*DD;
    float* ap  = out + (size_t)2*BT*DD;
#pragma unroll
    for (int i = 0; i < 8; i++) {
        int c = lane + i*32;
        float sc = ln_scale[c], bi = ln_bias[c];
        float ov = (v[i] - muv) * rv * sc + bi;
        float oa = (a[i] - mua) * ra * sc + bi;
        vp[row*DD + c]  = ov;
        ap[row*DD + c]  = oa;
        avp[row*DD + c] = 0.4f * (ov + oa);
    }
}

// ---------------- launch -----------------------------------------------------
extern "C" void kernel_launch(void* const* d_in, const int* in_sizes, int n_in,
                              void* d_out, int out_size) {
    const float* a_f  = (const float*)d_in[0];
    const float* v_f  = (const float*)d_in[1];
    const float* thr  = (const float*)d_in[2];
    const float* Wv1  = (const float*)d_in[3];
    const float* Wv2  = (const float*)d_in[4];
    const float* Wvfc = (const float*)d_in[5];
    const float* Wa1  = (const float*)d_in[6];
    const float* Wa2  = (const float*)d_in[7];
    const float* Wac  = (const float*)d_in[8];
    const float* lns  = (const float*)d_in[9];
    const float* lnb  = (const float*)d_in[10];
    float* out = (float*)d_out;

    k_in_gemm<<<dim3(2, 128, 4), 256>>>(v_f, a_f, Wv1, Wv2, Wa1, Wa2);
    k_scores<<<dim3(16, 16, 8), 256>>>();
    k_rowsum<<<BT, 256>>>(thr, 0);
    k_colsum<<<dim3(8, 8), 256>>>(thr, 0);
    k_rowsum<<<BT, 256>>>(thr, 1);
    k_colsum<<<dim3(8, 8), 256>>>(thr, 1);
    k_agg_v<<<dim3(2, 16, 8), 256>>>(v_f, thr);
    k_agg_a<<<dim3(2, 16, 8), 256>>>(a_f, thr);
    k_out_gemm<<<dim3(2, 128, 2), 256>>>(Wvfc, Wac);
    k_ln<<<BT/8, 256>>>(lns, lnb, out);
}

// round 6
// speedup vs baseline: 3.1323x; 3.1323x over previous
#include <cuda_runtime.h>
#include <cuda_fp16.h>
#include <cstdint>

#define BB 8
#define TT 2048
#define DD 256
#define BT (BB*TT)           // 16384
#define EPS_SUM 1e-8f
#define EPS_LN  1e-6f

// ---------------- scratch (device globals; no allocations allowed) ----------
__device__ __half g_vb1[BT*DD];
__device__ __half g_vb2[BT*DD];
__device__ __half g_ab1[BT*DD];
__device__ __half g_ab2[BT*DD];
__device__ float  g_S[(size_t)BB*TT*TT];   // 134 MB scores (fp32 for mask fidelity)
__device__ float  g_vout[BT*DD];
__device__ float  g_aout[BT*DD];
__device__ float  g_tmpv[BT*DD];
__device__ float  g_tmpa[BT*DD];
__device__ float  g_srow[BT];
__device__ float  g_scol[BT];
__device__ float  g_mrow[BT];
__device__ float  g_mcol[BT];

// ---------------- tensor-core primitives ------------------------------------
__device__ __forceinline__ uint32_t sm_u32(const void* p) {
    return (uint32_t)__cvta_generic_to_shared(p);
}
__device__ __forceinline__ void ldsm4(uint32_t* r, uint32_t a) {
    asm volatile("ldmatrix.sync.aligned.m8n8.x4.shared.b16 {%0,%1,%2,%3},[%4];"
                 : "=r"(r[0]), "=r"(r[1]), "=r"(r[2]), "=r"(r[3]) : "r"(a));
}
__device__ __forceinline__ void ldsm4t(uint32_t* r, uint32_t a) {
    asm volatile("ldmatrix.sync.aligned.m8n8.x4.trans.shared.b16 {%0,%1,%2,%3},[%4];"
                 : "=r"(r[0]), "=r"(r[1]), "=r"(r[2]), "=r"(r[3]) : "r"(a));
}
__device__ __forceinline__ void mma16816(float* d, const uint32_t* a, const uint32_t* b) {
    asm volatile("mma.sync.aligned.m16n8k16.row.col.f32.f16.f16.f32 "
                 "{%0,%1,%2,%3},{%4,%5,%6,%7},{%8,%9},{%0,%1,%2,%3};"
                 : "+f"(d[0]), "+f"(d[1]), "+f"(d[2]), "+f"(d[3])
                 : "r"(a[0]), "r"(a[1]), "r"(a[2]), "r"(a[3]), "r"(b[0]), "r"(b[1]));
}

// SMEM layouts:
//   non-trans operand: [row][40]  (40-half row stride; conflict-free for ldmatrix)
//   trans operand:     [k][136]   (136-half row stride; conflict-free for ldmatrix.trans)
#define LDA 40
#define LDT 136

// Warp-level tile: block 128x128, 8 warps as 4(m) x 2(n), warp tile 32x64.
// ATR/BTR: 0 = non-trans ([x][LDA]), 1 = trans ([k][LDT]).
template<int ATR, int BTR>
__device__ __forceinline__ void warp_mma(const __half* As, const __half* Bs,
                                         float (&acc)[2][8][4], int lane, int wm, int wn, int kk) {
    uint32_t af[2][4], bf[4][4];
#pragma unroll
    for (int i = 0; i < 2; i++) {
        int mb = wm + i * 16;
        if (ATR == 0) {
            uint32_t addr = sm_u32(As + (mb + (lane & 15)) * LDA + kk + (lane >> 4) * 8);
            ldsm4(af[i], addr);
        } else {
            uint32_t addr = sm_u32(As + (kk + (lane & 7) + ((lane >> 4) & 1) * 8) * LDT
                                      + mb + ((lane >> 3) & 1) * 8);
            ldsm4t(af[i], addr);
        }
    }
#pragma unroll
    for (int jj = 0; jj < 4; jj++) {
        int nb = wn + jj * 16;
        if (BTR == 0) {
            uint32_t addr = sm_u32(Bs + (nb + (lane & 7) + ((lane >> 4) ? 8 : 0)) * LDA
                                      + kk + ((lane >> 3) & 1) * 8);
            ldsm4(bf[jj], addr);
        } else {
            uint32_t addr = sm_u32(Bs + (kk + (lane & 7) + ((lane >> 3) & 1) * 8) * LDT
                                      + nb + ((lane >> 4) ? 8 : 0));
            ldsm4t(bf[jj], addr);
        }
    }
#pragma unroll
    for (int i = 0; i < 2; i++)
#pragma unroll
        for (int jj = 0; jj < 4; jj++) {
            mma16816(acc[i][2*jj],     af[i], &bf[jj][0]);
            mma16816(acc[i][2*jj + 1], af[i], &bf[jj][2]);
        }
}

// ---------------- K1: four input GEMMs relu(X @ W^T) -> half -----------------
__global__ __launch_bounds__(256) void k_in_gemm(const float* __restrict__ v_f,
                                                 const float* __restrict__ a_f,
                                                 const float* __restrict__ Wv1,
                                                 const float* __restrict__ Wv2,
                                                 const float* __restrict__ Wa1,
                                                 const float* __restrict__ Wa2) {
    __shared__ __half As[128 * LDA];
    __shared__ __half Bs[128 * LDA];
    int z = blockIdx.z;
    const float* X = (z < 2) ? v_f : a_f;
    const float* W = (z == 0) ? Wv1 : (z == 1) ? Wv2 : (z == 2) ? Wa1 : Wa2;
    __half* C = (z == 0) ? g_vb1 : (z == 1) ? g_vb2 : (z == 2) ? g_ab1 : g_ab2;
    int m0 = blockIdx.y * 128, n0 = blockIdx.x * 128;
    int t = threadIdx.x, lane = t & 31, w = t >> 5;
    int wm = (w & 3) * 32, wn = (w >> 2) * 64;
    float acc[2][8][4] = {};

    for (int k0 = 0; k0 < DD; k0 += 32) {
#pragma unroll
        for (int it = 0; it < 4; it++) {
            int m = it * 32 + (t >> 3);
            int k4 = (t & 7) * 4;
            float4 xa = *(const float4*)&X[(m0 + m) * DD + k0 + k4];
            float4 wb = *(const float4*)&W[(n0 + m) * DD + k0 + k4];
            *(__half2*)&As[m * LDA + k4]     = __floats2half2_rn(xa.x, xa.y);
            *(__half2*)&As[m * LDA + k4 + 2] = __floats2half2_rn(xa.z, xa.w);
            *(__half2*)&Bs[m * LDA + k4]     = __floats2half2_rn(wb.x, wb.y);
            *(__half2*)&Bs[m * LDA + k4 + 2] = __floats2half2_rn(wb.z, wb.w);
        }
        __syncthreads();
        warp_mma<0,0>(As, Bs, acc, lane, wm, wn, 0);
        warp_mma<0,0>(As, Bs, acc, lane, wm, wn, 16);
        __syncthreads();
    }
#pragma unroll
    for (int i = 0; i < 2; i++) {
        int r = m0 + wm + i * 16 + (lane >> 2);
#pragma unroll
        for (int j = 0; j < 8; j++) {
            int c = n0 + wn + j * 8 + 2 * (lane & 3);
            float* d = acc[i][j];
            *(__half2*)&C[(size_t)r * DD + c] =
                __floats2half2_rn(fmaxf(d[0], 0.f), fmaxf(d[1], 0.f));
            *(__half2*)&C[(size_t)(r + 8) * DD + c] =
                __floats2half2_rn(fmaxf(d[2], 0.f), fmaxf(d[3], 0.f));
        }
    }
}

// ---------------- K2: S = relu(Vb2 @ Ab1^T / 16) + fused row/col sums --------
__global__ __launch_bounds__(256) void k_scores() {
    __shared__ __half As[128 * LDA];
    __shared__ __half Bs[128 * LDA];
    __shared__ float srow_s[128];
    __shared__ float scol_s[128];
    int b = blockIdx.z;
    const __half* A  = g_vb2 + (size_t)b * TT * DD;
    const __half* Bm = g_ab1 + (size_t)b * TT * DD;
    float* C = g_S + (size_t)b * TT * TT;
    int m0 = blockIdx.y * 128, n0 = blockIdx.x * 128;
    int t = threadIdx.x, lane = t & 31, w = t >> 5;
    int wm = (w & 3) * 32, wn = (w >> 2) * 64;
    if (t < 128) { srow_s[t] = 0.f; scol_s[t] = 0.f; }
    float acc[2][8][4] = {};

    for (int k0 = 0; k0 < DD; k0 += 32) {
#pragma unroll
        for (int it = 0; it < 4; it++) {
            int m = it * 32 + (t >> 3);
            int k4 = (t & 7) * 4;
            *(uint2*)&As[m * LDA + k4] = *(const uint2*)&A[(size_t)(m0 + m) * DD + k0 + k4];
            *(uint2*)&Bs[m * LDA + k4] = *(const uint2*)&Bm[(size_t)(n0 + m) * DD + k0 + k4];
        }
        __syncthreads();
        warp_mma<0,0>(As, Bs, acc, lane, wm, wn, 0);
        warp_mma<0,0>(As, Bs, acc, lane, wm, wn, 16);
        __syncthreads();
    }
#pragma unroll
    for (int i = 0; i < 2; i++) {
        int rl = wm + i * 16 + (lane >> 2);
#pragma unroll
        for (int j = 0; j < 8; j++) {
            int cl = wn + j * 8 + 2 * (lane & 3);
            float* d = acc[i][j];
            float v0 = fmaxf(d[0] * 0.0625f, 0.f);
            float v1 = fmaxf(d[1] * 0.0625f, 0.f);
            float v2 = fmaxf(d[2] * 0.0625f, 0.f);
            float v3 = fmaxf(d[3] * 0.0625f, 0.f);
            *(float2*)&C[(size_t)(m0 + rl) * TT + n0 + cl]     = make_float2(v0, v1);
            *(float2*)&C[(size_t)(m0 + rl + 8) * TT + n0 + cl] = make_float2(v2, v3);
            atomicAdd(&srow_s[rl],     v0 + v1);
            atomicAdd(&srow_s[rl + 8], v2 + v3);
            atomicAdd(&scol_s[cl],     v0 + v2);
            atomicAdd(&scol_s[cl + 1], v1 + v3);
        }
    }
    __syncthreads();
    if (t < 128) {
        atomicAdd(&g_srow[b * TT + m0 + t], srow_s[t]);
        atomicAdd(&g_scol[b * TT + n0 + t], scol_s[t]);
    }
}

// ---------------- masked row sums --------------------------------------------
__global__ void k_mrow(const float* __restrict__ thr_p) {
    int row = blockIdx.x;                           // b*2048 + v
    const float* p = g_S + (size_t)row * TT;
    float tr = thr_p[0] * (g_srow[row] + EPS_SUM);
    float s = 0.f;
    for (int i = threadIdx.x; i < TT; i += 256) {
        float x = p[i];
        if (x > tr) s += x;
    }
    __shared__ float red[256];
    red[threadIdx.x] = s;
    __syncthreads();
    for (int st = 128; st > 0; st >>= 1) {
        if (threadIdx.x < st) red[threadIdx.x] += red[threadIdx.x + st];
        __syncthreads();
    }
    if (threadIdx.x == 0) g_mrow[row] = red[0];
}

// ---------------- masked col sums (row-split for occupancy) -------------------
__global__ void k_mcol(const float* __restrict__ thr_p) {
    int b = blockIdx.y;
    int a = blockIdx.x * 256 + threadIdx.x;
    int r0 = blockIdx.z * 256;
    float tr = thr_p[0] * (g_scol[b * TT + a] + EPS_SUM);
    const float* base = g_S + (size_t)b * TT * TT + (size_t)r0 * TT + a;
    float s = 0.f;
#pragma unroll 8
    for (int v = 0; v < 256; v++) {
        float x = base[(size_t)v * TT];
        if (x > tr) s += x;
    }
    atomicAdd(&g_mcol[b * TT + a], s);
}

// ---------------- K4: v_out = v_f + (masked S) @ Ab2 * rcp_row ----------------
__global__ __launch_bounds__(256) void k_agg_v(const float* __restrict__ v_f,
                                               const float* __restrict__ thr_p) {
    __shared__ __half As[128 * LDA];
    __shared__ __half Bst[32 * LDT];
    __shared__ float trs[128];
    int b = blockIdx.z, m0 = blockIdx.y * 128, n0 = blockIdx.x * 128;
    int t = threadIdx.x, lane = t & 31, w = t >> 5;
    int wm = (w & 3) * 32, wn = (w >> 2) * 64;
    if (t < 128) trs[t] = thr_p[0] * (g_srow[b * TT + m0 + t] + EPS_SUM);
    __syncthreads();
    const float* Sb = g_S + (size_t)b * TT * TT;
    const __half* Bg = g_ab2 + (size_t)b * TT * DD;
    float acc[2][8][4] = {};

    for (int k0 = 0; k0 < TT; k0 += 32) {
#pragma unroll
        for (int it = 0; it < 4; it++) {
            int m = it * 32 + (t >> 3);
            int k4 = (t & 7) * 4;
            float4 x = *(const float4*)&Sb[(size_t)(m0 + m) * TT + k0 + k4];
            float tr = trs[m];
            *(__half2*)&As[m * LDA + k4] =
                __floats2half2_rn(x.x > tr ? x.x : 0.f, x.y > tr ? x.y : 0.f);
            *(__half2*)&As[m * LDA + k4 + 2] =
                __floats2half2_rn(x.z > tr ? x.z : 0.f, x.w > tr ? x.w : 0.f);
        }
#pragma unroll
        for (int it = 0; it < 2; it++) {
            int k = it * 16 + (t >> 4);
            int n8 = (t & 15) * 8;
            *(uint4*)&Bst[k * LDT + n8] = *(const uint4*)&Bg[(size_t)(k0 + k) * DD + n0 + n8];
        }
        __syncthreads();
        warp_mma<0,1>(As, Bst, acc, lane, wm, wn, 0);
        warp_mma<0,1>(As, Bst, acc, lane, wm, wn, 16);
        __syncthreads();
    }
#pragma unroll
    for (int i = 0; i < 2; i++) {
        int rl = wm + i * 16 + (lane >> 2);
        int row0 = b * TT + m0 + rl;
        int row8 = row0 + 8;
        float rcp0 = 1.f / (g_mrow[row0] + EPS_SUM * (g_srow[row0] + EPS_SUM));
        float rcp8 = 1.f / (g_mrow[row8] + EPS_SUM * (g_srow[row8] + EPS_SUM));
#pragma unroll
        for (int j = 0; j < 8; j++) {
            int c = n0 + wn + j * 8 + 2 * (lane & 3);
            float* d = acc[i][j];
            size_t o0 = (size_t)row0 * DD + c;
            size_t o8 = (size_t)row8 * DD + c;
            g_vout[o0]     = v_f[o0]     + d[0] * rcp0;
            g_vout[o0 + 1] = v_f[o0 + 1] + d[1] * rcp0;
            g_vout[o8]     = v_f[o8]     + d[2] * rcp8;
            g_vout[o8 + 1] = v_f[o8 + 1] + d[3] * rcp8;
        }
    }
}

// ---------------- K5: a_out = a_f + (masked S)^T @ Vb1 * rcp_col --------------
__global__ __launch_bounds__(256) void k_agg_a(const float* __restrict__ a_f,
                                               const float* __restrict__ thr_p) {
    __shared__ __half Ast[32 * LDT];
    __shared__ __half Bst[32 * LDT];
    __shared__ float tcs[128];
    int b = blockIdx.z, m0 = blockIdx.y * 128, n0 = blockIdx.x * 128;
    int t = threadIdx.x, lane = t & 31, w = t >> 5;
    int wm = (w & 3) * 32, wn = (w >> 2) * 64;
    if (t < 128) tcs[t] = thr_p[0] * (g_scol[b * TT + m0 + t] + EPS_SUM);
    __syncthreads();
    const float* Sb = g_S + (size_t)b * TT * TT;
    const __half* Bg = g_vb1 + (size_t)b * TT * DD;
    float acc[2][8][4] = {};

    for (int k0 = 0; k0 < TT; k0 += 32) {
#pragma unroll
        for (int it = 0; it < 2; it++) {
            int k = it * 16 + (t >> 4);
            int m8 = (t & 15) * 8;
            const float* src = &Sb[(size_t)(k0 + k) * TT + m0 + m8];
            float4 x0 = *(const float4*)src;
            float4 x1 = *(const float4*)(src + 4);
            __half2 hh[4];
            hh[0] = __floats2half2_rn(x0.x > tcs[m8]     ? x0.x : 0.f,
                                      x0.y > tcs[m8 + 1] ? x0.y : 0.f);
            hh[1] = __floats2half2_rn(x0.z > tcs[m8 + 2] ? x0.z : 0.f,
                                      x0.w > tcs[m8 + 3] ? x0.w : 0.f);
            hh[2] = __floats2half2_rn(x1.x > tcs[m8 + 4] ? x1.x : 0.f,
                                      x1.y > tcs[m8 + 5] ? x1.y : 0.f);
            hh[3] = __floats2half2_rn(x1.z > tcs[m8 + 6] ? x1.z : 0.f,
                                      x1.w > tcs[m8 + 7] ? x1.w : 0.f);
            *(uint4*)&Ast[k * LDT + m8] = *(uint4*)hh;
        }
#pragma unroll
        for (int it = 0; it < 2; it++) {
            int k = it * 16 + (t >> 4);
            int n8 = (t & 15) * 8;
            *(uint4*)&Bst[k * LDT + n8] = *(const uint4*)&Bg[(size_t)(k0 + k) * DD + n0 + n8];
        }
        __syncthreads();
        warp_mma<1,1>(Ast, Bst, acc, lane, wm, wn, 0);
        warp_mma<1,1>(Ast, Bst, acc, lane, wm, wn, 16);
        __syncthreads();
    }
#pragma unroll
    for (int i = 0; i < 2; i++) {
        int rl = wm + i * 16 + (lane >> 2);
        int row0 = b * TT + m0 + rl;
        int row8 = row0 + 8;
        float rcp0 = 1.f / (g_mcol[row0] + EPS_SUM * (g_scol[row0] + EPS_SUM));
        float rcp8 = 1.f / (g_mcol[row8] + EPS_SUM * (g_scol[row8] + EPS_SUM));
#pragma unroll
        for (int j = 0; j < 8; j++) {
            int c = n0 + wn + j * 8 + 2 * (lane & 3);
            float* d = acc[i][j];
            size_t o0 = (size_t)row0 * DD + c;
            size_t o8 = (size_t)row8 * DD + c;
            g_aout[o0]     = a_f[o0]     + d[0] * rcp0;
            g_aout[o0 + 1] = a_f[o0 + 1] + d[1] * rcp0;
            g_aout[o8]     = a_f[o8]     + d[2] * rcp8;
            g_aout[o8 + 1] = a_f[o8 + 1] + d[3] * rcp8;
        }
    }
}

// ---------------- K6: output GEMMs relu(X @ W^T) -> float --------------------
__global__ __launch_bounds__(256) void k_out_gemm(const float* __restrict__ Wvfc,
                                                  const float* __restrict__ Wac) {
    __shared__ __half As[128 * LDA];
    __shared__ __half Bs[128 * LDA];
    int z = blockIdx.z;
    const float* X = z ? g_aout : g_vout;
    const float* W = z ? Wac : Wvfc;
    float* C = z ? g_tmpa : g_tmpv;
    int m0 = blockIdx.y * 128, n0 = blockIdx.x * 128;
    int t = threadIdx.x, lane = t & 31, w = t >> 5;
    int wm = (w & 3) * 32, wn = (w >> 2) * 64;
    float acc[2][8][4] = {};

    for (int k0 = 0; k0 < DD; k0 += 32) {
#pragma unroll
        for (int it = 0; it < 4; it++) {
            int m = it * 32 + (t >> 3);
            int k4 = (t & 7) * 4;
            float4 xa = *(const float4*)&X[(m0 + m) * DD + k0 + k4];
            float4 wb = *(const float4*)&W[(n0 + m) * DD + k0 + k4];
            *(__half2*)&As[m * LDA + k4]     = __floats2half2_rn(xa.x, xa.y);
            *(__half2*)&As[m * LDA + k4 + 2] = __floats2half2_rn(xa.z, xa.w);
            *(__half2*)&Bs[m * LDA + k4]     = __floats2half2_rn(wb.x, wb.y);
            *(__half2*)&Bs[m * LDA + k4 + 2] = __floats2half2_rn(wb.z, wb.w);
        }
        __syncthreads();
        warp_mma<0,0>(As, Bs, acc, lane, wm, wn, 0);
        warp_mma<0,0>(As, Bs, acc, lane, wm, wn, 16);
        __syncthreads();
    }
#pragma unroll
    for (int i = 0; i < 2; i++) {
        int r = m0 + wm + i * 16 + (lane >> 2);
#pragma unroll
        for (int j = 0; j < 8; j++) {
            int c = n0 + wn + j * 8 + 2 * (lane & 3);
            float* d = acc[i][j];
            *(float2*)&C[(size_t)r * DD + c] =
                make_float2(fmaxf(d[0], 0.f), fmaxf(d[1], 0.f));
            *(float2*)&C[(size_t)(r + 8) * DD + c] =
                make_float2(fmaxf(d[2], 0.f), fmaxf(d[3], 0.f));
        }
    }
}

// ---------------- layernorm + combine ----------------------------------------
__global__ void k_ln(const float* __restrict__ ln_scale, const float* __restrict__ ln_bias,
                     float* __restrict__ out) {
    int row = blockIdx.x * 8 + (threadIdx.x >> 5);
    int lane = threadIdx.x & 31;
    const float* xv = g_tmpv + (size_t)row * DD;
    const float* xa = g_tmpa + (size_t)row * DD;
    float v[8], a[8];
#pragma unroll
    for (int i = 0; i < 8; i++) { v[i] = xv[lane + i*32]; a[i] = xa[lane + i*32]; }
    float sv = 0.f, sa = 0.f;
#pragma unroll
    for (int i = 0; i < 8; i++) { sv += v[i]; sa += a[i]; }
#pragma unroll
    for (int o = 16; o > 0; o >>= 1) {
        sv += __shfl_xor_sync(0xffffffffu, sv, o);
        sa += __shfl_xor_sync(0xffffffffu, sa, o);
    }
    float muv = sv * (1.f/256.f), mua = sa * (1.f/256.f);
    float qv = 0.f, qa = 0.f;
#pragma unroll
    for (int i = 0; i < 8; i++) {
        float dv = v[i] - muv; qv += dv*dv;
        float da = a[i] - mua; qa += da*da;
    }
#pragma unroll
    for (int o = 16; o > 0; o >>= 1) {
        qv += __shfl_xor_sync(0xffffffffu, qv, o);
        qa += __shfl_xor_sync(0xffffffffu, qa, o);
    }
    float rv = rsqrtf(qv * (1.f/256.f) + EPS_LN);
    float ra = rsqrtf(qa * (1.f/256.f) + EPS_LN);

    float* avp = out;
    float* vp  = out + (size_t)BT*DD;
    float* ap  = out + (size_t)2*BT*DD;
#pragma unroll
    for (int i = 0; i < 8; i++) {
        int c = lane + i*32;
        float sc = ln_scale[c], bi = ln_bias[c];
        float ov = (v[i] - muv) * rv * sc + bi;
        float oa = (a[i] - mua) * ra * sc + bi;
        vp[(size_t)row*DD + c]  = ov;
        ap[(size_t)row*DD + c]  = oa;
        avp[(size_t)row*DD + c] = 0.4f * (ov + oa);
    }
}

// ---------------- zero accumulators ------------------------------------------
__global__ void k_zero() {
    int i = blockIdx.x * 256 + threadIdx.x;
    g_srow[i] = 0.f;
    g_scol[i] = 0.f;
    g_mcol[i] = 0.f;
}

// ---------------- launch -----------------------------------------------------
extern "C" void kernel_launch(void* const* d_in, const int* in_sizes, int n_in,
                              void* d_out, int out_size) {
    const float* a_f  = (const float*)d_in[0];
    const float* v_f  = (const float*)d_in[1];
    const float* thr  = (const float*)d_in[2];
    const float* Wv1  = (const float*)d_in[3];
    const float* Wv2  = (const float*)d_in[4];
    const float* Wvfc = (const float*)d_in[5];
    const float* Wa1  = (const float*)d_in[6];
    const float* Wa2  = (const float*)d_in[7];
    const float* Wac  = (const float*)d_in[8];
    const float* lns  = (const float*)d_in[9];
    const float* lnb  = (const float*)d_in[10];
    float* out = (float*)d_out;

    k_zero<<<BT/256, 256>>>();
    k_in_gemm<<<dim3(2, 128, 4), 256>>>(v_f, a_f, Wv1, Wv2, Wa1, Wa2);
    k_scores<<<dim3(16, 16, 8), 256>>>();
    k_mrow<<<BT, 256>>>(thr);
    k_mcol<<<dim3(8, 8, 8), 256>>>(thr);
    k_agg_v<<<dim3(2, 16, 8), 256>>>(v_f, thr);
    k_agg_a<<<dim3(2, 16, 8), 256>>>(a_f, thr);
    k_out_gemm<<<dim3(2, 128, 2), 256>>>(Wvfc, Wac);
    k_ln<<<BT/8, 256>>>(lns, lnb, out);
}

// round 7
// speedup vs baseline: 3.4653x; 1.1063x over previous
#include <cuda_runtime.h>
#include <cuda_fp16.h>
#include <cstdint>

#define BB 8
#define TT 2048
#define DD 256
#define BT (BB*TT)           // 16384
#define EPS_SUM 1e-8f
#define EPS_LN  1e-6f

// ---------------- scratch (device globals; no allocations allowed) ----------
__device__ __half g_vb1[BT*DD];
__device__ __half g_vb2[BT*DD];
__device__ __half g_ab1[BT*DD];
__device__ __half g_ab2[BT*DD];
__device__ float  g_S[(size_t)BB*TT*TT];   // 134 MB scores (fp32 for mask fidelity)
__device__ float  g_vout[BT*DD];
__device__ float  g_aout[BT*DD];
__device__ float  g_srow[BT];
__device__ float  g_scol[BT];

// ---------------- tensor-core primitives ------------------------------------
__device__ __forceinline__ uint32_t sm_u32(const void* p) {
    return (uint32_t)__cvta_generic_to_shared(p);
}
__device__ __forceinline__ void ldsm4(uint32_t* r, uint32_t a) {
    asm volatile("ldmatrix.sync.aligned.m8n8.x4.shared.b16 {%0,%1,%2,%3},[%4];"
                 : "=r"(r[0]), "=r"(r[1]), "=r"(r[2]), "=r"(r[3]) : "r"(a));
}
__device__ __forceinline__ void ldsm4t(uint32_t* r, uint32_t a) {
    asm volatile("ldmatrix.sync.aligned.m8n8.x4.trans.shared.b16 {%0,%1,%2,%3},[%4];"
                 : "=r"(r[0]), "=r"(r[1]), "=r"(r[2]), "=r"(r[3]) : "r"(a));
}
__device__ __forceinline__ void mma16816(float* d, const uint32_t* a, const uint32_t* b) {
    asm volatile("mma.sync.aligned.m16n8k16.row.col.f32.f16.f16.f32 "
                 "{%0,%1,%2,%3},{%4,%5,%6,%7},{%8,%9},{%0,%1,%2,%3};"
                 : "+f"(d[0]), "+f"(d[1]), "+f"(d[2]), "+f"(d[3])
                 : "r"(a[0]), "r"(a[1]), "r"(a[2]), "r"(a[3]), "r"(b[0]), "r"(b[1]));
}

#define LDA 40
#define LDT 136

// Warp tile 32 x 64. ATR/BTR: 0 = non-trans ([x][LDA]), 1 = trans ([k][LDT]).
template<int ATR, int BTR>
__device__ __forceinline__ void warp_mma(const __half* As, const __half* Bs,
                                         float (&acc)[2][8][4], int lane, int wm, int wn, int kk) {
    uint32_t af[2][4], bf[4][4];
#pragma unroll
    for (int i = 0; i < 2; i++) {
        int mb = wm + i * 16;
        if (ATR == 0) {
            uint32_t addr = sm_u32(As + (mb + (lane & 15)) * LDA + kk + (lane >> 4) * 8);
            ldsm4(af[i], addr);
        } else {
            uint32_t addr = sm_u32(As + (kk + (lane & 7) + ((lane >> 4) & 1) * 8) * LDT
                                      + mb + ((lane >> 3) & 1) * 8);
            ldsm4t(af[i], addr);
        }
    }
#pragma unroll
    for (int jj = 0; jj < 4; jj++) {
        int nb = wn + jj * 16;
        if (BTR == 0) {
            uint32_t addr = sm_u32(Bs + (nb + (lane & 7) + ((lane >> 4) ? 8 : 0)) * LDA
                                      + kk + ((lane >> 3) & 1) * 8);
            ldsm4(bf[jj], addr);
        } else {
            uint32_t addr = sm_u32(Bs + (kk + (lane & 7) + ((lane >> 3) & 1) * 8) * LDT
                                      + nb + ((lane >> 4) ? 8 : 0));
            ldsm4t(bf[jj], addr);
        }
    }
#pragma unroll
    for (int i = 0; i < 2; i++)
#pragma unroll
        for (int jj = 0; jj < 4; jj++) {
            mma16816(acc[i][2*jj],     af[i], &bf[jj][0]);
            mma16816(acc[i][2*jj + 1], af[i], &bf[jj][2]);
        }
}

// ---------------- K1: four input GEMMs relu(X @ W^T) -> half -----------------
__global__ __launch_bounds__(256) void k_in_gemm(const float* __restrict__ v_f,
                                                 const float* __restrict__ a_f,
                                                 const float* __restrict__ Wv1,
                                                 const float* __restrict__ Wv2,
                                                 const float* __restrict__ Wa1,
                                                 const float* __restrict__ Wa2) {
    __shared__ __half As[128 * LDA];
    __shared__ __half Bs[128 * LDA];
    int z = blockIdx.z;
    const float* X = (z < 2) ? v_f : a_f;
    const float* W = (z == 0) ? Wv1 : (z == 1) ? Wv2 : (z == 2) ? Wa1 : Wa2;
    __half* C = (z == 0) ? g_vb1 : (z == 1) ? g_vb2 : (z == 2) ? g_ab1 : g_ab2;
    int m0 = blockIdx.y * 128, n0 = blockIdx.x * 128;
    int t = threadIdx.x, lane = t & 31, w = t >> 5;
    int wm = (w & 3) * 32, wn = (w >> 2) * 64;
    float acc[2][8][4] = {};

    for (int k0 = 0; k0 < DD; k0 += 32) {
#pragma unroll
        for (int it = 0; it < 4; it++) {
            int m = it * 32 + (t >> 3);
            int k4 = (t & 7) * 4;
            float4 xa = *(const float4*)&X[(m0 + m) * DD + k0 + k4];
            float4 wb = *(const float4*)&W[(n0 + m) * DD + k0 + k4];
            *(__half2*)&As[m * LDA + k4]     = __floats2half2_rn(xa.x, xa.y);
            *(__half2*)&As[m * LDA + k4 + 2] = __floats2half2_rn(xa.z, xa.w);
            *(__half2*)&Bs[m * LDA + k4]     = __floats2half2_rn(wb.x, wb.y);
            *(__half2*)&Bs[m * LDA + k4 + 2] = __floats2half2_rn(wb.z, wb.w);
        }
        __syncthreads();
        warp_mma<0,0>(As, Bs, acc, lane, wm, wn, 0);
        warp_mma<0,0>(As, Bs, acc, lane, wm, wn, 16);
        __syncthreads();
    }
#pragma unroll
    for (int i = 0; i < 2; i++) {
        int r = m0 + wm + i * 16 + (lane >> 2);
#pragma unroll
        for (int j = 0; j < 8; j++) {
            int c = n0 + wn + j * 8 + 2 * (lane & 3);
            float* d = acc[i][j];
            *(__half2*)&C[(size_t)r * DD + c] =
                __floats2half2_rn(fmaxf(d[0], 0.f), fmaxf(d[1], 0.f));
            *(__half2*)&C[(size_t)(r + 8) * DD + c] =
                __floats2half2_rn(fmaxf(d[2], 0.f), fmaxf(d[3], 0.f));
        }
    }
}

// ---------------- K2: S = relu(Vb2 @ Ab1^T / 16) + fused row/col sums --------
__global__ __launch_bounds__(256) void k_scores() {
    __shared__ __half As[128 * LDA];
    __shared__ __half Bs[128 * LDA];
    __shared__ float srow_s[128];
    __shared__ float scol_s[128];
    int b = blockIdx.z;
    const __half* A  = g_vb2 + (size_t)b * TT * DD;
    const __half* Bm = g_ab1 + (size_t)b * TT * DD;
    float* C = g_S + (size_t)b * TT * TT;
    int m0 = blockIdx.y * 128, n0 = blockIdx.x * 128;
    int t = threadIdx.x, lane = t & 31, w = t >> 5;
    int wm = (w & 3) * 32, wn = (w >> 2) * 64;
    if (t < 128) { srow_s[t] = 0.f; scol_s[t] = 0.f; }
    float acc[2][8][4] = {};

    for (int k0 = 0; k0 < DD; k0 += 32) {
#pragma unroll
        for (int it = 0; it < 4; it++) {
            int m = it * 32 + (t >> 3);
            int k4 = (t & 7) * 4;
            *(uint2*)&As[m * LDA + k4] = *(const uint2*)&A[(size_t)(m0 + m) * DD + k0 + k4];
            *(uint2*)&Bs[m * LDA + k4] = *(const uint2*)&Bm[(size_t)(n0 + m) * DD + k0 + k4];
        }
        __syncthreads();
        warp_mma<0,0>(As, Bs, acc, lane, wm, wn, 0);
        warp_mma<0,0>(As, Bs, acc, lane, wm, wn, 16);
        __syncthreads();
    }
#pragma unroll
    for (int i = 0; i < 2; i++) {
        int rl = wm + i * 16 + (lane >> 2);
#pragma unroll
        for (int j = 0; j < 8; j++) {
            int cl = wn + j * 8 + 2 * (lane & 3);
            float* d = acc[i][j];
            float v0 = fmaxf(d[0] * 0.0625f, 0.f);
            float v1 = fmaxf(d[1] * 0.0625f, 0.f);
            float v2 = fmaxf(d[2] * 0.0625f, 0.f);
            float v3 = fmaxf(d[3] * 0.0625f, 0.f);
            *(float2*)&C[(size_t)(m0 + rl) * TT + n0 + cl]     = make_float2(v0, v1);
            *(float2*)&C[(size_t)(m0 + rl + 8) * TT + n0 + cl] = make_float2(v2, v3);
            atomicAdd(&srow_s[rl],     v0 + v1);
            atomicAdd(&srow_s[rl + 8], v2 + v3);
            atomicAdd(&scol_s[cl],     v0 + v2);
            atomicAdd(&scol_s[cl + 1], v1 + v3);
        }
    }
    __syncthreads();
    if (t < 128) {
        atomicAdd(&g_srow[b * TT + m0 + t], srow_s[t]);
        atomicAdd(&g_scol[b * TT + n0 + t], scol_s[t]);
    }
}

// ---------------- K4: v_out = v_f + (masked S) @ Ab2 * rcp_row ----------------
// masked row sums computed in-block from the S tiles already being loaded.
__global__ __launch_bounds__(256) void k_agg_v(const float* __restrict__ v_f,
                                               const float* __restrict__ thr_p) {
    __shared__ __half As[128 * LDA];
    __shared__ __half Bst[32 * LDT];
    __shared__ float trs[128];
    __shared__ float ses[128];
    __shared__ float msum[128];
    int b = blockIdx.z, m0 = blockIdx.y * 128, n0 = blockIdx.x * 128;
    int t = threadIdx.x, lane = t & 31, w = t >> 5;
    int wm = (w & 3) * 32, wn = (w >> 2) * 64;
    if (t < 128) {
        float s = g_srow[b * TT + m0 + t] + EPS_SUM;
        ses[t] = s;
        trs[t] = thr_p[0] * s;
        msum[t] = 0.f;
    }
    __syncthreads();
    const float* Sb = g_S + (size_t)b * TT * TT;
    const __half* Bg = g_ab2 + (size_t)b * TT * DD;
    float acc[2][8][4] = {};
    float macc[4] = {0.f, 0.f, 0.f, 0.f};

    for (int k0 = 0; k0 < TT; k0 += 32) {
#pragma unroll
        for (int it = 0; it < 4; it++) {
            int m = it * 32 + (t >> 3);
            int k4 = (t & 7) * 4;
            float4 x = *(const float4*)&Sb[(size_t)(m0 + m) * TT + k0 + k4];
            float tr = trs[m];
            float x0 = x.x > tr ? x.x : 0.f;
            float x1 = x.y > tr ? x.y : 0.f;
            float x2 = x.z > tr ? x.z : 0.f;
            float x3 = x.w > tr ? x.w : 0.f;
            macc[it] += (x0 + x1) + (x2 + x3);
            *(__half2*)&As[m * LDA + k4]     = __floats2half2_rn(x0, x1);
            *(__half2*)&As[m * LDA + k4 + 2] = __floats2half2_rn(x2, x3);
        }
#pragma unroll
        for (int it = 0; it < 2; it++) {
            int k = it * 16 + (t >> 4);
            int n8 = (t & 15) * 8;
            *(uint4*)&Bst[k * LDT + n8] = *(const uint4*)&Bg[(size_t)(k0 + k) * DD + n0 + n8];
        }
        __syncthreads();
        warp_mma<0,1>(As, Bst, acc, lane, wm, wn, 0);
        warp_mma<0,1>(As, Bst, acc, lane, wm, wn, 16);
        __syncthreads();
    }
    // combine per-thread masked-row partials (8 threads per row)
#pragma unroll
    for (int it = 0; it < 4; it++)
        atomicAdd(&msum[it * 32 + (t >> 3)], macc[it]);
    __syncthreads();
#pragma unroll
    for (int i = 0; i < 2; i++) {
        int rl = wm + i * 16 + (lane >> 2);
        int row0 = b * TT + m0 + rl;
        int row8 = row0 + 8;
        float rcp0 = 1.f / (msum[rl]     + EPS_SUM * ses[rl]);
        float rcp8 = 1.f / (msum[rl + 8] + EPS_SUM * ses[rl + 8]);
#pragma unroll
        for (int j = 0; j < 8; j++) {
            int c = n0 + wn + j * 8 + 2 * (lane & 3);
            float* d = acc[i][j];
            size_t o0 = (size_t)row0 * DD + c;
            size_t o8 = (size_t)row8 * DD + c;
            g_vout[o0]     = v_f[o0]     + d[0] * rcp0;
            g_vout[o0 + 1] = v_f[o0 + 1] + d[1] * rcp0;
            g_vout[o8]     = v_f[o8]     + d[2] * rcp8;
            g_vout[o8 + 1] = v_f[o8 + 1] + d[3] * rcp8;
        }
    }
}

// ---------------- K5: a_out = a_f + (masked S)^T @ Vb1 * rcp_col --------------
// masked col sums computed in-block from the S tiles already being loaded.
__global__ __launch_bounds__(256) void k_agg_a(const float* __restrict__ a_f,
                                               const float* __restrict__ thr_p) {
    __shared__ __half Ast[32 * LDT];
    __shared__ __half Bst[32 * LDT];
    __shared__ float tcs[128];
    __shared__ float ces[128];
    __shared__ float msum[128];
    int b = blockIdx.z, m0 = blockIdx.y * 128, n0 = blockIdx.x * 128;
    int t = threadIdx.x, lane = t & 31, w = t >> 5;
    int wm = (w & 3) * 32, wn = (w >> 2) * 64;
    if (t < 128) {
        float s = g_scol[b * TT + m0 + t] + EPS_SUM;
        ces[t] = s;
        tcs[t] = thr_p[0] * s;
        msum[t] = 0.f;
    }
    __syncthreads();
    const float* Sb = g_S + (size_t)b * TT * TT;
    const __half* Bg = g_vb1 + (size_t)b * TT * DD;
    float acc[2][8][4] = {};
    float cacc[8] = {};
    int m8 = (t & 15) * 8;

    for (int k0 = 0; k0 < TT; k0 += 32) {
#pragma unroll
        for (int it = 0; it < 2; it++) {
            int k = it * 16 + (t >> 4);
            const float* src = &Sb[(size_t)(k0 + k) * TT + m0 + m8];
            float4 x0 = *(const float4*)src;
            float4 x1 = *(const float4*)(src + 4);
            float v0 = x0.x > tcs[m8]     ? x0.x : 0.f;
            float v1 = x0.y > tcs[m8 + 1] ? x0.y : 0.f;
            float v2 = x0.z > tcs[m8 + 2] ? x0.z : 0.f;
            float v3 = x0.w > tcs[m8 + 3] ? x0.w : 0.f;
            float v4 = x1.x > tcs[m8 + 4] ? x1.x : 0.f;
            float v5 = x1.y > tcs[m8 + 5] ? x1.y : 0.f;
            float v6 = x1.z > tcs[m8 + 6] ? x1.z : 0.f;
            float v7 = x1.w > tcs[m8 + 7] ? x1.w : 0.f;
            cacc[0] += v0; cacc[1] += v1; cacc[2] += v2; cacc[3] += v3;
            cacc[4] += v4; cacc[5] += v5; cacc[6] += v6; cacc[7] += v7;
            __half2 hh[4];
            hh[0] = __floats2half2_rn(v0, v1);
            hh[1] = __floats2half2_rn(v2, v3);
            hh[2] = __floats2half2_rn(v4, v5);
            hh[3] = __floats2half2_rn(v6, v7);
            *(uint4*)&Ast[k * LDT + m8] = *(uint4*)hh;
        }
#pragma unroll
        for (int it = 0; it < 2; it++) {
            int k = it * 16 + (t >> 4);
            int n8 = (t & 15) * 8;
            *(uint4*)&Bst[k * LDT + n8] = *(const uint4*)&Bg[(size_t)(k0 + k) * DD + n0 + n8];
        }
        __syncthreads();
        warp_mma<1,1>(Ast, Bst, acc, lane, wm, wn, 0);
        warp_mma<1,1>(Ast, Bst, acc, lane, wm, wn, 16);
        __syncthreads();
    }
    // combine per-thread masked-col partials (16 threads per column)
#pragma unroll
    for (int q = 0; q < 8; q++)
        atomicAdd(&msum[m8 + q], cacc[q]);
    __syncthreads();
#pragma unroll
    for (int i = 0; i < 2; i++) {
        int rl = wm + i * 16 + (lane >> 2);
        int row0 = b * TT + m0 + rl;
        int row8 = row0 + 8;
        float rcp0 = 1.f / (msum[rl]     + EPS_SUM * ces[rl]);
        float rcp8 = 1.f / (msum[rl + 8] + EPS_SUM * ces[rl + 8]);
#pragma unroll
        for (int j = 0; j < 8; j++) {
            int c = n0 + wn + j * 8 + 2 * (lane & 3);
            float* d = acc[i][j];
            size_t o0 = (size_t)row0 * DD + c;
            size_t o8 = (size_t)row8 * DD + c;
            g_aout[o0]     = a_f[o0]     + d[0] * rcp0;
            g_aout[o0 + 1] = a_f[o0 + 1] + d[1] * rcp0;
            g_aout[o8]     = a_f[o8]     + d[2] * rcp8;
            g_aout[o8 + 1] = a_f[o8 + 1] + d[3] * rcp8;
        }
    }
}

// ---------------- K6: fused output GEMMs + relu + layernorm + combine --------
// Block tile 64 rows x 256 cols (full N). 8 warps as 2(m) x 4(n).
__global__ __launch_bounds__(256) void k_out_ln(const float* __restrict__ Wvfc,
                                                const float* __restrict__ Wac,
                                                const float* __restrict__ lns,
                                                const float* __restrict__ lnb,
                                                float* __restrict__ out) {
    __shared__ __half As[64 * LDA];
    __shared__ __half Bs[256 * LDA];
    __shared__ float rsum[64];
    __shared__ float rsq[64];
    __shared__ float scs[256];
    __shared__ float bis[256];
    int m0 = blockIdx.x * 64;
    int t = threadIdx.x, lane = t & 31, w = t >> 5;
    int wm = (w & 1) * 32, wn = (w >> 1) * 64;
    scs[t] = lns[t];
    bis[t] = lnb[t];

    float accv[2][8][4] = {};
    float acca[2][8][4] = {};

    for (int z = 0; z < 2; z++) {
        const float* X = z ? g_aout : g_vout;
        const float* W = z ? Wac : Wvfc;
        float (&acc)[2][8][4] = z ? acca : accv;

        for (int k0 = 0; k0 < DD; k0 += 32) {
            int k4 = (t & 7) * 4;
#pragma unroll
            for (int it = 0; it < 2; it++) {
                int m = it * 32 + (t >> 3);
                float4 xa = *(const float4*)&X[(size_t)(m0 + m) * DD + k0 + k4];
                *(__half2*)&As[m * LDA + k4]     = __floats2half2_rn(xa.x, xa.y);
                *(__half2*)&As[m * LDA + k4 + 2] = __floats2half2_rn(xa.z, xa.w);
            }
#pragma unroll
            for (int it = 0; it < 8; it++) {
                int n = it * 32 + (t >> 3);
                float4 wb = *(const float4*)&W[(size_t)n * DD + k0 + k4];
                *(__half2*)&Bs[n * LDA + k4]     = __floats2half2_rn(wb.x, wb.y);
                *(__half2*)&Bs[n * LDA + k4 + 2] = __floats2half2_rn(wb.z, wb.w);
            }
            __syncthreads();
            warp_mma<0,0>(As, Bs, acc, lane, wm, wn, 0);
            warp_mma<0,0>(As, Bs, acc, lane, wm, wn, 16);
            __syncthreads();
        }

        // relu + per-row sum/sumsq partials
        if (t < 64) { rsum[t] = 0.f; rsq[t] = 0.f; }
        __syncthreads();
#pragma unroll
        for (int i = 0; i < 2; i++) {
            float ps0 = 0.f, pq0 = 0.f, ps1 = 0.f, pq1 = 0.f;
#pragma unroll
            for (int j = 0; j < 8; j++) {
                float* d = acc[i][j];
                d[0] = fmaxf(d[0], 0.f); d[1] = fmaxf(d[1], 0.f);
                d[2] = fmaxf(d[2], 0.f); d[3] = fmaxf(d[3], 0.f);
                ps0 += d[0] + d[1]; pq0 += d[0]*d[0] + d[1]*d[1];
                ps1 += d[2] + d[3]; pq1 += d[2]*d[2] + d[3]*d[3];
            }
            int rl = wm + i * 16 + (lane >> 2);
            atomicAdd(&rsum[rl], ps0);     atomicAdd(&rsq[rl], pq0);
            atomicAdd(&rsum[rl + 8], ps1); atomicAdd(&rsq[rl + 8], pq1);
        }
        __syncthreads();

        // layernorm transform in place + write vp/ap (+ av on second pass)
        float* dst = out + (size_t)(z + 1) * BT * DD;
#pragma unroll
        for (int i = 0; i < 2; i++) {
#pragma unroll
            for (int h = 0; h < 2; h++) {
                int rl = wm + i * 16 + (lane >> 2) + h * 8;
                float mu = rsum[rl] * (1.f / 256.f);
                float var = rsq[rl] * (1.f / 256.f) - mu * mu;
                float rr = rsqrtf(var + EPS_LN);
                size_t rowoff = (size_t)(m0 + rl) * DD;
#pragma unroll
                for (int j = 0; j < 8; j++) {
                    int c = wn + j * 8 + 2 * (lane & 3);
                    float* d = acc[i][j];
                    float o0 = (d[h*2]     - mu) * rr * scs[c]     + bis[c];
                    float o1 = (d[h*2 + 1] - mu) * rr * scs[c + 1] + bis[c + 1];
                    d[h*2] = o0; d[h*2 + 1] = o1;
                    *(float2*)&dst[rowoff + c] = make_float2(o0, o1);
                    if (z == 1) {
                        float* dv = accv[i][j];
                        *(float2*)&out[rowoff + c] =
                            make_float2(0.4f * (o0 + dv[h*2]), 0.4f * (o1 + dv[h*2 + 1]));
                    }
                }
            }
        }
        __syncthreads();
    }
}

// ---------------- zero accumulators ------------------------------------------
__global__ void k_zero() {
    int i = blockIdx.x * 256 + threadIdx.x;
    g_srow[i] = 0.f;
    g_scol[i] = 0.f;
}

// ---------------- launch -----------------------------------------------------
extern "C" void kernel_launch(void* const* d_in, const int* in_sizes, int n_in,
                              void* d_out, int out_size) {
    const float* a_f  = (const float*)d_in[0];
    const float* v_f  = (const float*)d_in[1];
    const float* thr  = (const float*)d_in[2];
    const float* Wv1  = (const float*)d_in[3];
    const float* Wv2  = (const float*)d_in[4];
    const float* Wvfc = (const float*)d_in[5];
    const float* Wa1  = (const float*)d_in[6];
    const float* Wa2  = (const float*)d_in[7];
    const float* Wac  = (const float*)d_in[8];
    const float* lns  = (const float*)d_in[9];
    const float* lnb  = (const float*)d_in[10];
    float* out = (float*)d_out;

    k_zero<<<BT/256, 256>>>();
    k_in_gemm<<<dim3(2, 128, 4), 256>>>(v_f, a_f, Wv1, Wv2, Wa1, Wa2);
    k_scores<<<dim3(16, 16, 8), 256>>>();
    k_agg_v<<<dim3(2, 16, 8), 256>>>(v_f, thr);
    k_agg_a<<<dim3(2, 16, 8), 256>>>(a_f, thr);
    k_out_ln<<<BT/64, 256>>>(Wvfc, Wac, lns, lnb, out);
}

// round 8
// speedup vs baseline: 3.9719x; 1.1462x over previous
#include <cuda_runtime.h>
#include <cuda_fp16.h>
#include <cstdint>

#define BB 8
#define TT 2048
#define DD 256
#define BT (BB*TT)           // 16384
#define EPS_SUM 1e-8f
#define EPS_LN  1e-6f

// ---------------- scratch (device globals; no allocations allowed) ----------
__device__ __half g_vb1[BT*DD];
__device__ __half g_vb2[BT*DD];
__device__ __half g_ab1[BT*DD];
__device__ __half g_ab2[BT*DD];
__device__ __half g_S[(size_t)BB*TT*TT];   // 67 MB scores (fp16)
__device__ float  g_vout[BT*DD];
__device__ float  g_aout[BT*DD];
__device__ float  g_srow[BT];
__device__ float  g_scol[BT];

// ---------------- tensor-core primitives ------------------------------------
__device__ __forceinline__ uint32_t sm_u32(const void* p) {
    return (uint32_t)__cvta_generic_to_shared(p);
}
__device__ __forceinline__ void ldsm4(uint32_t* r, uint32_t a) {
    asm volatile("ldmatrix.sync.aligned.m8n8.x4.shared.b16 {%0,%1,%2,%3},[%4];"
                 : "=r"(r[0]), "=r"(r[1]), "=r"(r[2]), "=r"(r[3]) : "r"(a));
}
__device__ __forceinline__ void ldsm4t(uint32_t* r, uint32_t a) {
    asm volatile("ldmatrix.sync.aligned.m8n8.x4.trans.shared.b16 {%0,%1,%2,%3},[%4];"
                 : "=r"(r[0]), "=r"(r[1]), "=r"(r[2]), "=r"(r[3]) : "r"(a));
}
__device__ __forceinline__ void mma16816(float* d, const uint32_t* a, const uint32_t* b) {
    asm volatile("mma.sync.aligned.m16n8k16.row.col.f32.f16.f16.f32 "
                 "{%0,%1,%2,%3},{%4,%5,%6,%7},{%8,%9},{%0,%1,%2,%3};"
                 : "+f"(d[0]), "+f"(d[1]), "+f"(d[2]), "+f"(d[3])
                 : "r"(a[0]), "r"(a[1]), "r"(a[2]), "r"(a[3]), "r"(b[0]), "r"(b[1]));
}

#define LDA 40
#define LDT 136

// Warp tile 32 x 64. ATR/BTR: 0 = non-trans ([x][LDA]), 1 = trans ([k][LDT]).
template<int ATR, int BTR>
__device__ __forceinline__ void warp_mma(const __half* As, const __half* Bs,
                                         float (&acc)[2][8][4], int lane, int wm, int wn, int kk) {
    uint32_t af[2][4], bf[4][4];
#pragma unroll
    for (int i = 0; i < 2; i++) {
        int mb = wm + i * 16;
        if (ATR == 0) {
            uint32_t addr = sm_u32(As + (mb + (lane & 15)) * LDA + kk + (lane >> 4) * 8);
            ldsm4(af[i], addr);
        } else {
            uint32_t addr = sm_u32(As + (kk + (lane & 7) + ((lane >> 4) & 1) * 8) * LDT
                                      + mb + ((lane >> 3) & 1) * 8);
            ldsm4t(af[i], addr);
        }
    }
#pragma unroll
    for (int jj = 0; jj < 4; jj++) {
        int nb = wn + jj * 16;
        if (BTR == 0) {
            uint32_t addr = sm_u32(Bs + (nb + (lane & 7) + ((lane >> 4) ? 8 : 0)) * LDA
                                      + kk + ((lane >> 3) & 1) * 8);
            ldsm4(bf[jj], addr);
        } else {
            uint32_t addr = sm_u32(Bs + (kk + (lane & 7) + ((lane >> 3) & 1) * 8) * LDT
                                      + nb + ((lane >> 4) ? 8 : 0));
            ldsm4t(bf[jj], addr);
        }
    }
#pragma unroll
    for (int i = 0; i < 2; i++)
#pragma unroll
        for (int jj = 0; jj < 4; jj++) {
            mma16816(acc[i][2*jj],     af[i], &bf[jj][0]);
            mma16816(acc[i][2*jj + 1], af[i], &bf[jj][2]);
        }
}

// ---------------- K1: four input GEMMs relu(X @ W^T) -> half -----------------
__global__ __launch_bounds__(256) void k_in_gemm(const float* __restrict__ v_f,
                                                 const float* __restrict__ a_f,
                                                 const float* __restrict__ Wv1,
                                                 const float* __restrict__ Wv2,
                                                 const float* __restrict__ Wa1,
                                                 const float* __restrict__ Wa2) {
    __shared__ __half As[128 * LDA];
    __shared__ __half Bs[128 * LDA];
    int z = blockIdx.z;
    const float* X = (z < 2) ? v_f : a_f;
    const float* W = (z == 0) ? Wv1 : (z == 1) ? Wv2 : (z == 2) ? Wa1 : Wa2;
    __half* C = (z == 0) ? g_vb1 : (z == 1) ? g_vb2 : (z == 2) ? g_ab1 : g_ab2;
    int m0 = blockIdx.y * 128, n0 = blockIdx.x * 128;
    int t = threadIdx.x, lane = t & 31, w = t >> 5;
    int wm = (w & 3) * 32, wn = (w >> 2) * 64;
    float acc[2][8][4] = {};

    for (int k0 = 0; k0 < DD; k0 += 32) {
#pragma unroll
        for (int it = 0; it < 4; it++) {
            int m = it * 32 + (t >> 3);
            int k4 = (t & 7) * 4;
            float4 xa = *(const float4*)&X[(m0 + m) * DD + k0 + k4];
            float4 wb = *(const float4*)&W[(n0 + m) * DD + k0 + k4];
            *(__half2*)&As[m * LDA + k4]     = __floats2half2_rn(xa.x, xa.y);
            *(__half2*)&As[m * LDA + k4 + 2] = __floats2half2_rn(xa.z, xa.w);
            *(__half2*)&Bs[m * LDA + k4]     = __floats2half2_rn(wb.x, wb.y);
            *(__half2*)&Bs[m * LDA + k4 + 2] = __floats2half2_rn(wb.z, wb.w);
        }
        __syncthreads();
        warp_mma<0,0>(As, Bs, acc, lane, wm, wn, 0);
        warp_mma<0,0>(As, Bs, acc, lane, wm, wn, 16);
        __syncthreads();
    }
#pragma unroll
    for (int i = 0; i < 2; i++) {
        int r = m0 + wm + i * 16 + (lane >> 2);
#pragma unroll
        for (int j = 0; j < 8; j++) {
            int c = n0 + wn + j * 8 + 2 * (lane & 3);
            float* d = acc[i][j];
            *(__half2*)&C[(size_t)r * DD + c] =
                __floats2half2_rn(fmaxf(d[0], 0.f), fmaxf(d[1], 0.f));
            *(__half2*)&C[(size_t)(r + 8) * DD + c] =
                __floats2half2_rn(fmaxf(d[2], 0.f), fmaxf(d[3], 0.f));
        }
    }
}

// ---------------- K2: S = relu(Vb2 @ Ab1^T / 16) -> half, + row/col sums -----
// Double-buffered pipeline: global loads for tile k+1 issued before MMAs on k.
__global__ __launch_bounds__(256) void k_scores() {
    __shared__ __half As[2][128 * LDA];
    __shared__ __half Bs[2][128 * LDA];
    __shared__ float srow_s[128];
    __shared__ float scol_s[128];
    int b = blockIdx.z;
    const __half* A  = g_vb2 + (size_t)b * TT * DD;
    const __half* Bm = g_ab1 + (size_t)b * TT * DD;
    __half* C = g_S + (size_t)b * TT * TT;
    int m0 = blockIdx.y * 128, n0 = blockIdx.x * 128;
    int t = threadIdx.x, lane = t & 31, w = t >> 5;
    int wm = (w & 3) * 32, wn = (w >> 2) * 64;
    if (t < 128) { srow_s[t] = 0.f; scol_s[t] = 0.f; }
    int mld = t >> 3, k4 = (t & 7) * 4;
    float acc[2][8][4] = {};
    uint2 ra[4], rb[4];

    // prologue: tile 0 -> buf 0
#pragma unroll
    for (int it = 0; it < 4; it++) {
        int m = it * 32 + mld;
        ra[it] = *(const uint2*)&A[(size_t)(m0 + m) * DD + k4];
        rb[it] = *(const uint2*)&Bm[(size_t)(n0 + m) * DD + k4];
    }
#pragma unroll
    for (int it = 0; it < 4; it++) {
        int m = it * 32 + mld;
        *(uint2*)&As[0][m * LDA + k4] = ra[it];
        *(uint2*)&Bs[0][m * LDA + k4] = rb[it];
    }
    __syncthreads();

    for (int kt = 0; kt < 8; kt++) {
        int cur = kt & 1;
        if (kt < 7) {
            int k0 = (kt + 1) * 32;
#pragma unroll
            for (int it = 0; it < 4; it++) {
                int m = it * 32 + mld;
                ra[it] = *(const uint2*)&A[(size_t)(m0 + m) * DD + k0 + k4];
                rb[it] = *(const uint2*)&Bm[(size_t)(n0 + m) * DD + k0 + k4];
            }
        }
        warp_mma<0,0>(As[cur], Bs[cur], acc, lane, wm, wn, 0);
        warp_mma<0,0>(As[cur], Bs[cur], acc, lane, wm, wn, 16);
        if (kt < 7) {
#pragma unroll
            for (int it = 0; it < 4; it++) {
                int m = it * 32 + mld;
                *(uint2*)&As[cur ^ 1][m * LDA + k4] = ra[it];
                *(uint2*)&Bs[cur ^ 1][m * LDA + k4] = rb[it];
            }
        }
        __syncthreads();
    }

#pragma unroll
    for (int i = 0; i < 2; i++) {
        int rl = wm + i * 16 + (lane >> 2);
#pragma unroll
        for (int j = 0; j < 8; j++) {
            int cl = wn + j * 8 + 2 * (lane & 3);
            float* d = acc[i][j];
            float v0 = fmaxf(d[0] * 0.0625f, 0.f);
            float v1 = fmaxf(d[1] * 0.0625f, 0.f);
            float v2 = fmaxf(d[2] * 0.0625f, 0.f);
            float v3 = fmaxf(d[3] * 0.0625f, 0.f);
            *(__half2*)&C[(size_t)(m0 + rl) * TT + n0 + cl]     = __floats2half2_rn(v0, v1);
            *(__half2*)&C[(size_t)(m0 + rl + 8) * TT + n0 + cl] = __floats2half2_rn(v2, v3);
            atomicAdd(&srow_s[rl],     v0 + v1);
            atomicAdd(&srow_s[rl + 8], v2 + v3);
            atomicAdd(&scol_s[cl],     v0 + v2);
            atomicAdd(&scol_s[cl + 1], v1 + v3);
        }
    }
    __syncthreads();
    if (t < 128) {
        atomicAdd(&g_srow[b * TT + m0 + t], srow_s[t]);
        atomicAdd(&g_scol[b * TT + n0 + t], scol_s[t]);
    }
}

// mask 8 halfs (uint4) against threshold tr, accumulate masked sum into acc
__device__ __forceinline__ uint4 mask8(uint4 x, float tr, float& accm) {
    __half2* h = (__half2*)&x;
    uint4 r;
    __half2* o = (__half2*)&r;
#pragma unroll
    for (int i = 0; i < 4; i++) {
        float2 f = __half22float2(h[i]);
        float a0 = f.x > tr ? f.x : 0.f;
        float a1 = f.y > tr ? f.y : 0.f;
        accm += a0 + a1;
        o[i] = __floats2half2_rn(a0, a1);
    }
    return r;
}

// ---------------- K4: v_out = v_f + (masked S) @ Ab2 * rcp_row ----------------
// Double-buffered; masked row sums computed during the SMEM fill.
__global__ __launch_bounds__(256) void k_agg_v(const float* __restrict__ v_f,
                                               const float* __restrict__ thr_p) {
    __shared__ __half As[2][128 * LDA];
    __shared__ __half Bst[2][32 * LDT];
    __shared__ float trs[128];
    __shared__ float ses[128];
    __shared__ float msum[128];
    int b = blockIdx.z, m0 = blockIdx.y * 128, n0 = blockIdx.x * 128;
    int t = threadIdx.x, lane = t & 31, w = t >> 5;
    int wm = (w & 3) * 32, wn = (w >> 2) * 64;
    if (t < 128) {
        float s = g_srow[b * TT + m0 + t] + EPS_SUM;
        ses[t] = s;
        trs[t] = thr_p[0] * s;
        msum[t] = 0.f;
    }
    __syncthreads();
    const __half* Sb = g_S + (size_t)b * TT * TT;
    const __half* Bg = g_ab2 + (size_t)b * TT * DD;
    float acc[2][8][4] = {};
    float macc[2] = {0.f, 0.f};
    // S tile mapping: q in {0,1}: row = q*64 + (t>>2), seg = (t&3)*8
    int srow0 = t >> 2, sseg = (t & 3) * 8;
    // B tile mapping: q in {0,1}: k = q*16 + (t>>4), n8 = (t&15)*8
    int bk0 = t >> 4, bn8 = (t & 15) * 8;
    uint4 xs[2], br[2];

    // prologue: tile 0 -> buf 0
#pragma unroll
    for (int q = 0; q < 2; q++) {
        xs[q] = *(const uint4*)&Sb[(size_t)(m0 + q*64 + srow0) * TT + sseg];
        br[q] = *(const uint4*)&Bg[(size_t)(q*16 + bk0) * DD + n0 + bn8];
    }
#pragma unroll
    for (int q = 0; q < 2; q++) {
        int row = q*64 + srow0;
        *(uint4*)&As[0][row * LDA + sseg] = mask8(xs[q], trs[row], macc[q]);
        *(uint4*)&Bst[0][(q*16 + bk0) * LDT + bn8] = br[q];
    }
    __syncthreads();

    for (int kt = 0; kt < 64; kt++) {
        int cur = kt & 1;
        if (kt < 63) {
            int k0 = (kt + 1) * 32;
#pragma unroll
            for (int q = 0; q < 2; q++) {
                xs[q] = *(const uint4*)&Sb[(size_t)(m0 + q*64 + srow0) * TT + k0 + sseg];
                br[q] = *(const uint4*)&Bg[(size_t)(k0 + q*16 + bk0) * DD + n0 + bn8];
            }
        }
        warp_mma<0,1>(As[cur], Bst[cur], acc, lane, wm, wn, 0);
        warp_mma<0,1>(As[cur], Bst[cur], acc, lane, wm, wn, 16);
        if (kt < 63) {
#pragma unroll
            for (int q = 0; q < 2; q++) {
                int row = q*64 + srow0;
                *(uint4*)&As[cur ^ 1][row * LDA + sseg] = mask8(xs[q], trs[row], macc[q]);
                *(uint4*)&Bst[cur ^ 1][(q*16 + bk0) * LDT + bn8] = br[q];
            }
        }
        __syncthreads();
    }
    // combine per-thread masked-row partials (4 threads per row)
    atomicAdd(&msum[srow0],      macc[0]);
    atomicAdd(&msum[64 + srow0], macc[1]);
    __syncthreads();
#pragma unroll
    for (int i = 0; i < 2; i++) {
        int rl = wm + i * 16 + (lane >> 2);
        int row0 = b * TT + m0 + rl;
        int row8 = row0 + 8;
        float rcp0 = 1.f / (msum[rl]     + EPS_SUM * ses[rl]);
        float rcp8 = 1.f / (msum[rl + 8] + EPS_SUM * ses[rl + 8]);
#pragma unroll
        for (int j = 0; j < 8; j++) {
            int c = n0 + wn + j * 8 + 2 * (lane & 3);
            float* d = acc[i][j];
            size_t o0 = (size_t)row0 * DD + c;
            size_t o8 = (size_t)row8 * DD + c;
            g_vout[o0]     = v_f[o0]     + d[0] * rcp0;
            g_vout[o0 + 1] = v_f[o0 + 1] + d[1] * rcp0;
            g_vout[o8]     = v_f[o8]     + d[2] * rcp8;
            g_vout[o8 + 1] = v_f[o8 + 1] + d[3] * rcp8;
        }
    }
}

// ---------------- K5: a_out = a_f + (masked S)^T @ Vb1 * rcp_col --------------
// Double-buffered; masked col sums computed during the SMEM fill.
__global__ __launch_bounds__(256) void k_agg_a(const float* __restrict__ a_f,
                                               const float* __restrict__ thr_p) {
    __shared__ __half Ast[2][32 * LDT];
    __shared__ __half Bst[2][32 * LDT];
    __shared__ float tcs[128];
    __shared__ float ces[128];
    __shared__ float msum[128];
    int b = blockIdx.z, m0 = blockIdx.y * 128, n0 = blockIdx.x * 128;
    int t = threadIdx.x, lane = t & 31, w = t >> 5;
    int wm = (w & 3) * 32, wn = (w >> 2) * 64;
    if (t < 128) {
        float s = g_scol[b * TT + m0 + t] + EPS_SUM;
        ces[t] = s;
        tcs[t] = thr_p[0] * s;
        msum[t] = 0.f;
    }
    __syncthreads();
    const __half* Sb = g_S + (size_t)b * TT * TT;
    const __half* Bg = g_vb1 + (size_t)b * TT * DD;
    float acc[2][8][4] = {};
    float cacc[8] = {};
    // S^T tile mapping: q in {0,1}: k = q*16 + (t>>4), m8 = (t&15)*8 (fixed per thread)
    int sk0 = t >> 4, m8 = (t & 15) * 8;
    uint4 xs[2], br[2];

    // masked store for one S^T uint4 (per-column thresholds)
    auto maskc = [&](uint4 x) {
        __half2* h = (__half2*)&x;
        uint4 r;
        __half2* o = (__half2*)&r;
#pragma unroll
        for (int i = 0; i < 4; i++) {
            float2 f = __half22float2(h[i]);
            float a0 = f.x > tcs[m8 + 2*i]     ? f.x : 0.f;
            float a1 = f.y > tcs[m8 + 2*i + 1] ? f.y : 0.f;
            cacc[2*i]     += a0;
            cacc[2*i + 1] += a1;
            o[i] = __floats2half2_rn(a0, a1);
        }
        return r;
    };

    // prologue: tile 0 -> buf 0
#pragma unroll
    for (int q = 0; q < 2; q++) {
        xs[q] = *(const uint4*)&Sb[(size_t)(q*16 + sk0) * TT + m0 + m8];
        br[q] = *(const uint4*)&Bg[(size_t)(q*16 + sk0) * DD + n0 + m8];
    }
#pragma unroll
    for (int q = 0; q < 2; q++) {
        *(uint4*)&Ast[0][(q*16 + sk0) * LDT + m8] = maskc(xs[q]);
        *(uint4*)&Bst[0][(q*16 + sk0) * LDT + m8] = br[q];
    }
    __syncthreads();

    for (int kt = 0; kt < 64; kt++) {
        int cur = kt & 1;
        if (kt < 63) {
            int k0 = (kt + 1) * 32;
#pragma unroll
            for (int q = 0; q < 2; q++) {
                xs[q] = *(const uint4*)&Sb[(size_t)(k0 + q*16 + sk0) * TT + m0 + m8];
                br[q] = *(const uint4*)&Bg[(size_t)(k0 + q*16 + sk0) * DD + n0 + m8];
            }
        }
        warp_mma<1,1>(Ast[cur], Bst[cur], acc, lane, wm, wn, 0);
        warp_mma<1,1>(Ast[cur], Bst[cur], acc, lane, wm, wn, 16);
        if (kt < 63) {
#pragma unroll
            for (int q = 0; q < 2; q++) {
                *(uint4*)&Ast[cur ^ 1][(q*16 + sk0) * LDT + m8] = maskc(xs[q]);
                *(uint4*)&Bst[cur ^ 1][(q*16 + sk0) * LDT + m8] = br[q];
            }
        }
        __syncthreads();
    }
    // combine per-thread masked-col partials (16 threads per column)
#pragma unroll
    for (int q = 0; q < 8; q++)
        atomicAdd(&msum[m8 + q], cacc[q]);
    __syncthreads();
#pragma unroll
    for (int i = 0; i < 2; i++) {
        int rl = wm + i * 16 + (lane >> 2);
        int row0 = b * TT + m0 + rl;
        int row8 = row0 + 8;
        float rcp0 = 1.f / (msum[rl]     + EPS_SUM * ces[rl]);
        float rcp8 = 1.f / (msum[rl + 8] + EPS_SUM * ces[rl + 8]);
#pragma unroll
        for (int j = 0; j < 8; j++) {
            int c = n0 + wn + j * 8 + 2 * (lane & 3);
            float* d = acc[i][j];
            size_t o0 = (size_t)row0 * DD + c;
            size_t o8 = (size_t)row8 * DD + c;
            g_aout[o0]     = a_f[o0]     + d[0] * rcp0;
            g_aout[o0 + 1] = a_f[o0 + 1] + d[1] * rcp0;
            g_aout[o8]     = a_f[o8]     + d[2] * rcp8;
            g_aout[o8 + 1] = a_f[o8 + 1] + d[3] * rcp8;
        }
    }
}

// ---------------- K6: fused output GEMMs + relu + layernorm + combine --------
// Block tile 64 rows x 256 cols (full N). 8 warps as 2(m) x 4(n).
__global__ __launch_bounds__(256) void k_out_ln(const float* __restrict__ Wvfc,
                                                const float* __restrict__ Wac,
                                                const float* __restrict__ lns,
                                                const float* __restrict__ lnb,
                                                float* __restrict__ out) {
    __shared__ __half As[64 * LDA];
    __shared__ __half Bs[256 * LDA];
    __shared__ float rsum[64];
    __shared__ float rsq[64];
    __shared__ float scs[256];
    __shared__ float bis[256];
    int m0 = blockIdx.x * 64;
    int t = threadIdx.x, lane = t & 31, w = t >> 5;
    int wm = (w & 1) * 32, wn = (w >> 1) * 64;
    scs[t] = lns[t];
    bis[t] = lnb[t];

    float accv[2][8][4] = {};
    float acca[2][8][4] = {};

    for (int z = 0; z < 2; z++) {
        const float* X = z ? g_aout : g_vout;
        const float* W = z ? Wac : Wvfc;
        float (&acc)[2][8][4] = z ? acca : accv;

        for (int k0 = 0; k0 < DD; k0 += 32) {
            int k4 = (t & 7) * 4;
#pragma unroll
            for (int it = 0; it < 2; it++) {
                int m = it * 32 + (t >> 3);
                float4 xa = *(const float4*)&X[(size_t)(m0 + m) * DD + k0 + k4];
                *(__half2*)&As[m * LDA + k4]     = __floats2half2_rn(xa.x, xa.y);
                *(__half2*)&As[m * LDA + k4 + 2] = __floats2half2_rn(xa.z, xa.w);
            }
#pragma unroll
            for (int it = 0; it < 8; it++) {
                int n = it * 32 + (t >> 3);
                float4 wb = *(const float4*)&W[(size_t)n * DD + k0 + k4];
                *(__half2*)&Bs[n * LDA + k4]     = __floats2half2_rn(wb.x, wb.y);
                *(__half2*)&Bs[n * LDA + k4 + 2] = __floats2half2_rn(wb.z, wb.w);
            }
            __syncthreads();
            warp_mma<0,0>(As, Bs, acc, lane, wm, wn, 0);
            warp_mma<0,0>(As, Bs, acc, lane, wm, wn, 16);
            __syncthreads();
        }

        // relu + per-row sum/sumsq partials
        if (t < 64) { rsum[t] = 0.f; rsq[t] = 0.f; }
        __syncthreads();
#pragma unroll
        for (int i = 0; i < 2; i++) {
            float ps0 = 0.f, pq0 = 0.f, ps1 = 0.f, pq1 = 0.f;
#pragma unroll
            for (int j = 0; j < 8; j++) {
                float* d = acc[i][j];
                d[0] = fmaxf(d[0], 0.f); d[1] = fmaxf(d[1], 0.f);
                d[2] = fmaxf(d[2], 0.f); d[3] = fmaxf(d[3], 0.f);
                ps0 += d[0] + d[1]; pq0 += d[0]*d[0] + d[1]*d[1];
                ps1 += d[2] + d[3]; pq1 += d[2]*d[2] + d[3]*d[3];
            }
            int rl = wm + i * 16 + (lane >> 2);
            atomicAdd(&rsum[rl], ps0);     atomicAdd(&rsq[rl], pq0);
            atomicAdd(&rsum[rl + 8], ps1); atomicAdd(&rsq[rl + 8], pq1);
        }
        __syncthreads();

        // layernorm transform in place + write vp/ap (+ av on second pass)
        float* dst = out + (size_t)(z + 1) * BT * DD;
#pragma unroll
        for (int i = 0; i < 2; i++) {
#pragma unroll
            for (int h = 0; h < 2; h++) {
                int rl = wm + i * 16 + (lane >> 2) + h * 8;
                float mu = rsum[rl] * (1.f / 256.f);
                float var = rsq[rl] * (1.f / 256.f) - mu * mu;
                float rr = rsqrtf(var + EPS_LN);
                size_t rowoff = (size_t)(m0 + rl) * DD;
#pragma unroll
                for (int j = 0; j < 8; j++) {
                    int c = wn + j * 8 + 2 * (lane & 3);
                    float* d = acc[i][j];
                    float o0 = (d[h*2]     - mu) * rr * scs[c]     + bis[c];
                    float o1 = (d[h*2 + 1] - mu) * rr * scs[c + 1] + bis[c + 1];
                    d[h*2] = o0; d[h*2 + 1] = o1;
                    *(float2*)&dst[rowoff + c] = make_float2(o0, o1);
                    if (z == 1) {
                        float* dv = accv[i][j];
                        *(float2*)&out[rowoff + c] =
                            make_float2(0.4f * (o0 + dv[h*2]), 0.4f * (o1 + dv[h*2 + 1]));
                    }
                }
            }
        }
        __syncthreads();
    }
}

// ---------------- zero accumulators ------------------------------------------
__global__ void k_zero() {
    int i = blockIdx.x * 256 + threadIdx.x;
    g_srow[i] = 0.f;
    g_scol[i] = 0.f;
}

// ---------------- launch -----------------------------------------------------
extern "C" void kernel_launch(void* const* d_in, const int* in_sizes, int n_in,
                              void* d_out, int out_size) {
    const float* a_f  = (const float*)d_in[0];
    const float* v_f  = (const float*)d_in[1];
    const float* thr  = (const float*)d_in[2];
    const float* Wv1  = (const float*)d_in[3];
    const float* Wv2  = (const float*)d_in[4];
    const float* Wvfc = (const float*)d_in[5];
    const float* Wa1  = (const float*)d_in[6];
    const float* Wa2  = (const float*)d_in[7];
    const float* Wac  = (const float*)d_in[8];
    const float* lns  = (const float*)d_in[9];
    const float* lnb  = (const float*)d_in[10];
    float* out = (float*)d_out;

    k_zero<<<BT/256, 256>>>();
    k_in_gemm<<<dim3(2, 128, 4), 256>>>(v_f, a_f, Wv1, Wv2, Wa1, Wa2);
    k_scores<<<dim3(16, 16, 8), 256>>>();
    k_agg_v<<<dim3(2, 16, 8), 256>>>(v_f, thr);
    k_agg_a<<<dim3(2, 16, 8), 256>>>(a_f, thr);
    k_out_ln<<<BT/64, 256>>>(Wvfc, Wac, lns, lnb, out);
}